// round 12
// baseline (speedup 1.0000x reference)
#include <cuda_runtime.h>
#include <cuda_bf16.h>
#include <cstdint>

// Problem constants
#define S_LEN 2048
#define B_SZ  128
#define H_SZ  128
#define G_SZ  384   // 3*H
#define C_SZ  10
#define TCH_T 16    // timesteps per GEMM CTA

// Scratch: xp (input projections, reused by both layers) and y0 (layer-0 output seq)
__device__ float g_xp[(size_t)S_LEN * B_SZ * G_SZ];   // [(t*B + b)*3H + g]
__device__ float g_y0[(size_t)S_LEN * B_SZ * H_SZ];   // [(t*B + b)*H + j]

// ---- packed dual-fp32 helpers -------------------------------------------
__device__ __forceinline__ unsigned long long fma2(unsigned long long a,
                                                   unsigned long long b,
                                                   unsigned long long c) {
    unsigned long long d;
    asm("fma.rn.f32x2 %0, %1, %2, %3;" : "=l"(d) : "l"(a), "l"(b), "l"(c));
    return d;
}
__device__ __forceinline__ float lo32(unsigned long long v) {
    return __uint_as_float((unsigned)(v & 0xffffffffull));
}
__device__ __forceinline__ float hi32(unsigned long long v) {
    return __uint_as_float((unsigned)(v >> 32));
}

// ---- mma.sync / ldmatrix helpers (plain sm_80+ features, no 'a'-gating) ---
__device__ __forceinline__ uint32_t smem_u32(const void* p) {
    uint32_t a;
    asm("{ .reg .u64 t; cvta.to.shared.u64 t, %1; cvt.u32.u64 %0, t; }"
        : "=r"(a) : "l"(p));
    return a;
}
__device__ __forceinline__ void ldmx4(uint32_t* r, uint32_t addr) {
    asm volatile("ldmatrix.sync.aligned.m8n8.x4.shared.b16 {%0,%1,%2,%3}, [%4];"
                 : "=r"(r[0]), "=r"(r[1]), "=r"(r[2]), "=r"(r[3]) : "r"(addr));
}
__device__ __forceinline__ void mma_bf16(float* c, const uint32_t* a,
                                         uint32_t b0, uint32_t b1) {
    asm volatile(
        "mma.sync.aligned.m16n8k16.row.col.f32.bf16.bf16.f32 "
        "{%0,%1,%2,%3}, {%4,%5,%6,%7}, {%8,%9}, {%0,%1,%2,%3};"
        : "+f"(c[0]), "+f"(c[1]), "+f"(c[2]), "+f"(c[3])
        : "r"(a[0]), "r"(a[1]), "r"(a[2]), "r"(a[3]), "r"(b0), "r"(b1));
}

// Split one float4 into bf16 hi + lo pairs (packed as uint2 = 4 bf16)
__device__ __forceinline__ void split4(float4 v, uint2& hi, uint2& lo) {
    __nv_bfloat162 h01 = __floats2bfloat162_rn(v.x, v.y);
    __nv_bfloat162 h23 = __floats2bfloat162_rn(v.z, v.w);
    const float r0 = v.x - __bfloat162float(h01.x);
    const float r1 = v.y - __bfloat162float(h01.y);
    const float r2 = v.z - __bfloat162float(h23.x);
    const float r3 = v.w - __bfloat162float(h23.y);
    __nv_bfloat162 l01 = __floats2bfloat162_rn(r0, r1);
    __nv_bfloat162 l23 = __floats2bfloat162_rn(r2, r3);
    hi = make_uint2(*reinterpret_cast<uint32_t*>(&h01), *reinterpret_cast<uint32_t*>(&h23));
    lo = make_uint2(*reinterpret_cast<uint32_t*>(&l01), *reinterpret_cast<uint32_t*>(&l23));
}

// SMEM layout (bytes): bias + 2x double-buffered X tiles + W tiles, pitch 272 B
#define PITCHB 272
#define TILEB  (128 * PITCHB)          // 34816
#define SM_BIAS 0
#define SM_XHI0 512
#define SM_XLO0 (SM_XHI0 + TILEB)
#define SM_XHI1 (SM_XLO0 + TILEB)
#define SM_XLO1 (SM_XHI1 + TILEB)
#define SM_WHI  (SM_XLO1 + TILEB)
#define SM_WLO  (SM_WHI + TILEB)
#define SM_TOT  (SM_WLO + TILEB)       // 209408

// ---------------------------------------------------------------------------
// Tensor-core input-projection GEMM — unchanged from R11 (proven ~420 us).
// ---------------------------------------------------------------------------
__global__ __launch_bounds__(256, 1)
void gemm_mma_kernel(const float* __restrict__ in,
                     const float* __restrict__ W,
                     const float* __restrict__ bias,
                     float* __restrict__ out,
                     long strideB, long strideT)
{
    extern __shared__ __align__(16) char smem[];
    const uint32_t sb = smem_u32(smem);
    float* sbias = reinterpret_cast<float*>(smem + SM_BIAS);

    const int tid  = threadIdx.x;
    const int w    = tid >> 5;
    const int lane = tid & 31;
    const int tbase = blockIdx.x * TCH_T;
    const int g0    = blockIdx.y * 128;

    if (tid < 128) sbias[tid] = bias[g0 + tid];
    for (int i = tid; i < 128 * 32; i += 256) {
        const int row = i >> 5, c4 = i & 31;
        const float4 v = *reinterpret_cast<const float4*>(
            W + (size_t)(g0 + row) * H_SZ + c4 * 4);
        uint2 hi, lo;
        split4(v, hi, lo);
        const int off = row * PITCHB + c4 * 8;
        *reinterpret_cast<uint2*>(smem + SM_WHI + off) = hi;
        *reinterpret_cast<uint2*>(smem + SM_WLO + off) = lo;
    }

    {
        const int t0 = tbase;
#pragma unroll
        for (int k = 0; k < 16; k++) {
            const int i = tid + k * 256;
            const int row = i >> 5, c4 = i & 31;
            const float4 v = *reinterpret_cast<const float4*>(
                in + (size_t)row * strideB + (size_t)t0 * strideT + c4 * 4);
            uint2 hi, lo;
            split4(v, hi, lo);
            const int off = row * PITCHB + c4 * 8;
            *reinterpret_cast<uint2*>(smem + SM_XHI0 + off) = hi;
            *reinterpret_cast<uint2*>(smem + SM_XLO0 + off) = lo;
        }
    }
    __syncthreads();

    const int mBase = (w & 1) * 64;
    const int nBase = (w >> 1) * 32;

    uint32_t aoff[4];
#pragma unroll
    for (int mt = 0; mt < 4; mt++)
        aoff[mt] = (uint32_t)((mBase + mt * 16 + (lane & 15)) * PITCHB
                              + (lane >> 4) * 16);
    uint32_t boff[2];
#pragma unroll
    for (int nt2 = 0; nt2 < 2; nt2++) {
        const int rt = lane & 7, tl = lane >> 3;
        const int n = nBase + nt2 * 16 + ((tl >> 1) << 3) + rt;
        boff[nt2] = (uint32_t)(n * PITCHB + (tl & 1) * 16);
    }

    for (int tt = 0; tt < TCH_T; tt++) {
        const int t   = tbase + tt;
        const int cur = tt & 1;
        const uint32_t xhiC = cur ? SM_XHI1 : SM_XHI0;
        const uint32_t xloC = cur ? SM_XLO1 : SM_XLO0;
        const uint32_t xhiN = cur ? SM_XHI0 : SM_XHI1;
        const uint32_t xloN = cur ? SM_XLO0 : SM_XLO1;

        float4 v[16];
        const bool more = (tt + 1 < TCH_T);
        if (more) {
#pragma unroll
            for (int k = 0; k < 16; k++) {
                const int i = tid + k * 256;
                const int row = i >> 5, c4 = i & 31;
                v[k] = *reinterpret_cast<const float4*>(
                    in + (size_t)row * strideB + (size_t)(t + 1) * strideT + c4 * 4);
            }
        }

        float acc[4][4][4];
#pragma unroll
        for (int mt = 0; mt < 4; mt++)
#pragma unroll
            for (int nt = 0; nt < 4; nt++)
#pragma unroll
                for (int e = 0; e < 4; e++) acc[mt][nt][e] = 0.0f;

#pragma unroll
        for (int s = 0; s < 3; s++) {
            const uint32_t aS = sb + (s == 2 ? xloC : xhiC);
            const uint32_t bS = sb + (s == 1 ? SM_WLO : SM_WHI);

            uint32_t a[2][4][4], b[2][2][4];
#pragma unroll
            for (int mt = 0; mt < 4; mt++) ldmx4(a[0][mt], aS + aoff[mt]);
#pragma unroll
            for (int nt2 = 0; nt2 < 2; nt2++) ldmx4(b[0][nt2], bS + boff[nt2]);

#pragma unroll
            for (int k16 = 0; k16 < 8; k16++) {
                const int pc = k16 & 1;
                const int pn = pc ^ 1;
                if (k16 < 7) {
                    const uint32_t kb = (uint32_t)((k16 + 1) * 32);
#pragma unroll
                    for (int mt = 0; mt < 4; mt++) ldmx4(a[pn][mt], aS + aoff[mt] + kb);
#pragma unroll
                    for (int nt2 = 0; nt2 < 2; nt2++) ldmx4(b[pn][nt2], bS + boff[nt2] + kb);
                }
#pragma unroll
                for (int mt = 0; mt < 4; mt++)
#pragma unroll
                    for (int nt = 0; nt < 4; nt++)
                        mma_bf16(acc[mt][nt], a[pc][mt],
                                 b[pc][nt >> 1][(nt & 1) * 2],
                                 b[pc][nt >> 1][(nt & 1) * 2 + 1]);
            }
        }

        if (more) {
#pragma unroll
            for (int k = 0; k < 16; k++) {
                const int i = tid + k * 256;
                const int row = i >> 5, c4 = i & 31;
                uint2 hi, lo;
                split4(v[k], hi, lo);
                const int off = row * PITCHB + c4 * 8;
                *reinterpret_cast<uint2*>(smem + xhiN + off) = hi;
                *reinterpret_cast<uint2*>(smem + xloN + off) = lo;
            }
        }

        const int mrow = lane >> 2;
        const int ncol = (lane & 3) * 2;
#pragma unroll
        for (int mt = 0; mt < 4; mt++) {
#pragma unroll
            for (int nt = 0; nt < 4; nt++) {
                const int col = nBase + nt * 8 + ncol;
                const float bv0 = sbias[col], bv1 = sbias[col + 1];
                const int row0 = mBase + mt * 16 + mrow;
                float* p0 = out + ((size_t)t * B_SZ + row0) * G_SZ + g0 + col;
                float* p1 = p0 + (size_t)8 * G_SZ;
                *reinterpret_cast<float2*>(p0) =
                    make_float2(acc[mt][nt][0] + bv0, acc[mt][nt][1] + bv1);
                *reinterpret_cast<float2*>(p1) =
                    make_float2(acc[mt][nt][2] + bv0, acc[mt][nt][3] + bv1);
            }
        }
        __syncthreads();
    }
}

// ---------------------------------------------------------------------------
// Recurrent scan, 2 batches per CTA. 64 CTAs x 384 threads.
// Thread g holds W_hh[g][:] ONCE (batch-invariant!) and computes the g-th
// gate projection for BOTH batch chains (sequential dots, shared registers).
// Gate phase: warps 0-3 handle batch A, warps 4-7 handle batch B concurrently
// -> per-step tail (barriers + MUFU chains) amortized over 2 batches.
// ---------------------------------------------------------------------------
__global__ __launch_bounds__(384, 1)
void recur2_kernel(const float* __restrict__ xp,
                   const float* __restrict__ W_hh,
                   const float* __restrict__ b_hh,
                   int write_y,
                   const float* __restrict__ W_out,
                   const float* __restrict__ b_out,
                   float* __restrict__ out)
{
    __shared__ __align__(16) float h_sA[H_SZ];
    __shared__ __align__(16) float h_sB[H_SZ];
    __shared__ float hp_sA[G_SZ];
    __shared__ float hp_sB[G_SZ];
    __shared__ float xg_sA[G_SZ];
    __shared__ float xg_sB[G_SZ];

    const int bA = blockIdx.x * 2;
    const int bB = bA + 1;
    const int g  = threadIdx.x;

    unsigned long long w[64];
    const unsigned long long* wrow =
        reinterpret_cast<const unsigned long long*>(W_hh + (size_t)g * H_SZ);
#pragma unroll
    for (int i = 0; i < 64; i++) w[i] = wrow[i];
    const float bh = b_hh[g];

    if (g < H_SZ) { h_sA[g] = 0.0f; h_sB[g] = 0.0f; }

    const float* xptrA = xp + (size_t)bA * G_SZ + g;   // xptrB = xptrA + G_SZ
    float xnextA = __ldg(xptrA);
    float xnextB = __ldg(xptrA + G_SZ);
    __syncthreads();

    for (int t = 0; t < S_LEN; t++) {
        const float xcurA = xnextA;
        const float xcurB = xnextB;
        if (t + 1 < S_LEN) {
            const float* p = xptrA + (size_t)(t + 1) * B_SZ * G_SZ;
            xnextA = __ldg(p);
            xnextB = __ldg(p + G_SZ);
        }

        // Dot A: hpA[g] = h_A . W_hh[g]
        {
            unsigned long long a0 = 0ull, a1 = 0ull;
            const ulonglong2* hq = reinterpret_cast<const ulonglong2*>(h_sA);
#pragma unroll
            for (int i = 0; i < 32; i++) {
                const ulonglong2 q = hq[i];   // broadcast LDS.128
                a0 = fma2(q.x, w[2 * i + 0], a0);
                a1 = fma2(q.y, w[2 * i + 1], a1);
            }
            hp_sA[g] = lo32(a0) + hi32(a0) + lo32(a1) + hi32(a1) + bh;
            xg_sA[g] = xcurA;
        }
        // Dot B (registers reused)
        {
            unsigned long long a0 = 0ull, a1 = 0ull;
            const ulonglong2* hq = reinterpret_cast<const ulonglong2*>(h_sB);
#pragma unroll
            for (int i = 0; i < 32; i++) {
                const ulonglong2 q = hq[i];
                a0 = fma2(q.x, w[2 * i + 0], a0);
                a1 = fma2(q.y, w[2 * i + 1], a1);
            }
            hp_sB[g] = lo32(a0) + hi32(a0) + lo32(a1) + hi32(a1) + bh;
            xg_sB[g] = xcurB;
        }
        __syncthreads();

        if (g < H_SZ) {
            // Batch A gates on warps 0-3
            const float pr = xg_sA[g]            + hp_sA[g];
            const float pz = xg_sA[H_SZ + g]     + hp_sA[H_SZ + g];
            const float xn = xg_sA[2 * H_SZ + g];
            const float hn = hp_sA[2 * H_SZ + g];
            const float r = 1.0f / (1.0f + __expf(-pr));
            const float z = 1.0f / (1.0f + __expf(-pz));
            const float n = tanhf(fmaf(r, hn, xn));
            const float hold = h_sA[g];
            const float hnew = (1.0f - z) * n + z * hold;
            h_sA[g] = hnew;
            if (write_y)
                g_y0[((size_t)t * B_SZ + bA) * H_SZ + g] = hnew;
        } else if (g < 2 * H_SZ) {
            // Batch B gates on warps 4-7 (concurrent with A)
            const int j = g - H_SZ;
            const float pr = xg_sB[j]            + hp_sB[j];
            const float pz = xg_sB[H_SZ + j]     + hp_sB[H_SZ + j];
            const float xn = xg_sB[2 * H_SZ + j];
            const float hn = hp_sB[2 * H_SZ + j];
            const float r = 1.0f / (1.0f + __expf(-pr));
            const float z = 1.0f / (1.0f + __expf(-pz));
            const float n = tanhf(fmaf(r, hn, xn));
            const float hold = h_sB[j];
            const float hnew = (1.0f - z) * n + z * hold;
            h_sB[j] = hnew;
            if (write_y)
                g_y0[((size_t)t * B_SZ + bB) * H_SZ + j] = hnew;
        }
        __syncthreads();
    }

    // Fused final linear layer (layer 1 only)
    if (!write_y) {
        if (g < C_SZ) {
            float acc = b_out[g];
#pragma unroll 8
            for (int j = 0; j < H_SZ; j++)
                acc = fmaf(h_sA[j], W_out[g * H_SZ + j], acc);
            out[bA * C_SZ + g] = acc;
        } else if (g >= H_SZ && g < H_SZ + C_SZ) {
            const int c = g - H_SZ;
            float acc = b_out[c];
#pragma unroll 8
            for (int j = 0; j < H_SZ; j++)
                acc = fmaf(h_sB[j], W_out[c * H_SZ + j], acc);
            out[bB * C_SZ + c] = acc;
        }
    }
}

// ---------------------------------------------------------------------------
extern "C" void kernel_launch(void* const* d_in, const int* in_sizes, int n_in,
                              void* d_out, int out_size)
{
    const float* x     = (const float*)d_in[0];
    const float* W_ih0 = (const float*)d_in[1];
    const float* W_hh0 = (const float*)d_in[2];
    const float* b_ih0 = (const float*)d_in[3];
    const float* b_hh0 = (const float*)d_in[4];
    const float* W_ih1 = (const float*)d_in[5];
    const float* W_hh1 = (const float*)d_in[6];
    const float* b_ih1 = (const float*)d_in[7];
    const float* b_hh1 = (const float*)d_in[8];
    const float* W_out = (const float*)d_in[9];
    const float* b_out = (const float*)d_in[10];
    float* out = (float*)d_out;

    void* xp_ptr = nullptr;
    void* y0_ptr = nullptr;
    cudaGetSymbolAddress(&xp_ptr, g_xp);
    cudaGetSymbolAddress(&y0_ptr, g_y0);
    float* xp = (float*)xp_ptr;
    float* y0 = (float*)y0_ptr;

    cudaFuncSetAttribute(gemm_mma_kernel,
                         cudaFuncAttributeMaxDynamicSharedMemorySize, SM_TOT);

    const dim3 gemm_grid(S_LEN / TCH_T, 3);

    // Layer 0 input projection: x is [B, S, D] -> strideB = S*D, strideT = D
    gemm_mma_kernel<<<gemm_grid, 256, SM_TOT>>>(x, W_ih0, b_ih0, xp,
                                                (long)S_LEN * H_SZ, (long)H_SZ);
    // Layer 0 recurrence (writes y0): 64 CTAs x 2 batches
    recur2_kernel<<<B_SZ / 2, 384>>>(xp, W_hh0, b_hh0, 1, nullptr, nullptr, nullptr);

    // Layer 1 input projection: y0 is [(t*B + b)*H] -> strideB = H, strideT = B*H
    gemm_mma_kernel<<<gemm_grid, 256, SM_TOT>>>(y0, W_ih1, b_ih1, xp,
                                                (long)H_SZ, (long)B_SZ * H_SZ);
    // Layer 1 recurrence + fused output linear
    recur2_kernel<<<B_SZ / 2, 384>>>(xp, W_hh1, b_hh1, 0, W_out, b_out, out);
}

// round 13
// speedup vs baseline: 1.4698x; 1.4698x over previous
#include <cuda_runtime.h>
#include <cuda_bf16.h>
#include <cstdint>

// Problem constants
#define S_LEN 2048
#define B_SZ  128
#define H_SZ  128
#define G_SZ  384   // 3*H
#define C_SZ  10
#define TCH_T 16    // timesteps per GEMM CTA

// Scratch: xp (input projections, reused by both layers) and y0 (layer-0 output seq)
__device__ float g_xp[(size_t)S_LEN * B_SZ * G_SZ];   // [(t*B + b)*3H + g]
__device__ float g_y0[(size_t)S_LEN * B_SZ * H_SZ];   // [(t*B + b)*H + j]

// ---- packed dual-fp32 helpers -------------------------------------------
__device__ __forceinline__ unsigned long long fma2(unsigned long long a,
                                                   unsigned long long b,
                                                   unsigned long long c) {
    unsigned long long d;
    asm("fma.rn.f32x2 %0, %1, %2, %3;" : "=l"(d) : "l"(a), "l"(b), "l"(c));
    return d;
}
__device__ __forceinline__ unsigned long long add2(unsigned long long a,
                                                   unsigned long long b) {
    unsigned long long d;
    asm("add.rn.f32x2 %0, %1, %2;" : "=l"(d) : "l"(a), "l"(b));
    return d;
}
__device__ __forceinline__ float lo32(unsigned long long v) {
    return __uint_as_float((unsigned)(v & 0xffffffffull));
}
__device__ __forceinline__ float hi32(unsigned long long v) {
    return __uint_as_float((unsigned)(v >> 32));
}

// ---- mma.sync / ldmatrix helpers (plain sm_80+ features, no 'a'-gating) ---
__device__ __forceinline__ uint32_t smem_u32(const void* p) {
    uint32_t a;
    asm("{ .reg .u64 t; cvta.to.shared.u64 t, %1; cvt.u32.u64 %0, t; }"
        : "=r"(a) : "l"(p));
    return a;
}
__device__ __forceinline__ void ldmx4(uint32_t* r, uint32_t addr) {
    asm volatile("ldmatrix.sync.aligned.m8n8.x4.shared.b16 {%0,%1,%2,%3}, [%4];"
                 : "=r"(r[0]), "=r"(r[1]), "=r"(r[2]), "=r"(r[3]) : "r"(addr));
}
__device__ __forceinline__ void mma_bf16(float* c, const uint32_t* a,
                                         uint32_t b0, uint32_t b1) {
    asm volatile(
        "mma.sync.aligned.m16n8k16.row.col.f32.bf16.bf16.f32 "
        "{%0,%1,%2,%3}, {%4,%5,%6,%7}, {%8,%9}, {%0,%1,%2,%3};"
        : "+f"(c[0]), "+f"(c[1]), "+f"(c[2]), "+f"(c[3])
        : "r"(a[0]), "r"(a[1]), "r"(a[2]), "r"(a[3]), "r"(b0), "r"(b1));
}

// Split one float4 into bf16 hi + lo pairs (packed as uint2 = 4 bf16)
__device__ __forceinline__ void split4(float4 v, uint2& hi, uint2& lo) {
    __nv_bfloat162 h01 = __floats2bfloat162_rn(v.x, v.y);
    __nv_bfloat162 h23 = __floats2bfloat162_rn(v.z, v.w);
    const float r0 = v.x - __bfloat162float(h01.x);
    const float r1 = v.y - __bfloat162float(h01.y);
    const float r2 = v.z - __bfloat162float(h23.x);
    const float r3 = v.w - __bfloat162float(h23.y);
    __nv_bfloat162 l01 = __floats2bfloat162_rn(r0, r1);
    __nv_bfloat162 l23 = __floats2bfloat162_rn(r2, r3);
    hi = make_uint2(*reinterpret_cast<uint32_t*>(&h01), *reinterpret_cast<uint32_t*>(&h23));
    lo = make_uint2(*reinterpret_cast<uint32_t*>(&l01), *reinterpret_cast<uint32_t*>(&l23));
}

// SMEM layout (bytes): bias + 2x double-buffered X tiles + W tiles, pitch 272 B
#define PITCHB 272
#define TILEB  (128 * PITCHB)          // 34816
#define SM_BIAS 0
#define SM_XHI0 512
#define SM_XLO0 (SM_XHI0 + TILEB)
#define SM_XHI1 (SM_XLO0 + TILEB)
#define SM_XLO1 (SM_XHI1 + TILEB)
#define SM_WHI  (SM_XLO1 + TILEB)
#define SM_WLO  (SM_WHI + TILEB)
#define SM_TOT  (SM_WLO + TILEB)       // 209408

// ---------------------------------------------------------------------------
// Tensor-core input-projection GEMM — unchanged from R11 (proven ~420 us).
// ---------------------------------------------------------------------------
__global__ __launch_bounds__(256, 1)
void gemm_mma_kernel(const float* __restrict__ in,
                     const float* __restrict__ W,
                     const float* __restrict__ bias,
                     float* __restrict__ out,
                     long strideB, long strideT)
{
    extern __shared__ __align__(16) char smem[];
    const uint32_t sb = smem_u32(smem);
    float* sbias = reinterpret_cast<float*>(smem + SM_BIAS);

    const int tid  = threadIdx.x;
    const int w    = tid >> 5;
    const int lane = tid & 31;
    const int tbase = blockIdx.x * TCH_T;
    const int g0    = blockIdx.y * 128;

    if (tid < 128) sbias[tid] = bias[g0 + tid];
    for (int i = tid; i < 128 * 32; i += 256) {
        const int row = i >> 5, c4 = i & 31;
        const float4 v = *reinterpret_cast<const float4*>(
            W + (size_t)(g0 + row) * H_SZ + c4 * 4);
        uint2 hi, lo;
        split4(v, hi, lo);
        const int off = row * PITCHB + c4 * 8;
        *reinterpret_cast<uint2*>(smem + SM_WHI + off) = hi;
        *reinterpret_cast<uint2*>(smem + SM_WLO + off) = lo;
    }

    {
        const int t0 = tbase;
#pragma unroll
        for (int k = 0; k < 16; k++) {
            const int i = tid + k * 256;
            const int row = i >> 5, c4 = i & 31;
            const float4 v = *reinterpret_cast<const float4*>(
                in + (size_t)row * strideB + (size_t)t0 * strideT + c4 * 4);
            uint2 hi, lo;
            split4(v, hi, lo);
            const int off = row * PITCHB + c4 * 8;
            *reinterpret_cast<uint2*>(smem + SM_XHI0 + off) = hi;
            *reinterpret_cast<uint2*>(smem + SM_XLO0 + off) = lo;
        }
    }
    __syncthreads();

    const int mBase = (w & 1) * 64;
    const int nBase = (w >> 1) * 32;

    uint32_t aoff[4];
#pragma unroll
    for (int mt = 0; mt < 4; mt++)
        aoff[mt] = (uint32_t)((mBase + mt * 16 + (lane & 15)) * PITCHB
                              + (lane >> 4) * 16);
    uint32_t boff[2];
#pragma unroll
    for (int nt2 = 0; nt2 < 2; nt2++) {
        const int rt = lane & 7, tl = lane >> 3;
        const int n = nBase + nt2 * 16 + ((tl >> 1) << 3) + rt;
        boff[nt2] = (uint32_t)(n * PITCHB + (tl & 1) * 16);
    }

    for (int tt = 0; tt < TCH_T; tt++) {
        const int t   = tbase + tt;
        const int cur = tt & 1;
        const uint32_t xhiC = cur ? SM_XHI1 : SM_XHI0;
        const uint32_t xloC = cur ? SM_XLO1 : SM_XLO0;
        const uint32_t xhiN = cur ? SM_XHI0 : SM_XHI1;
        const uint32_t xloN = cur ? SM_XLO0 : SM_XLO1;

        float4 v[16];
        const bool more = (tt + 1 < TCH_T);
        if (more) {
#pragma unroll
            for (int k = 0; k < 16; k++) {
                const int i = tid + k * 256;
                const int row = i >> 5, c4 = i & 31;
                v[k] = *reinterpret_cast<const float4*>(
                    in + (size_t)row * strideB + (size_t)(t + 1) * strideT + c4 * 4);
            }
        }

        float acc[4][4][4];
#pragma unroll
        for (int mt = 0; mt < 4; mt++)
#pragma unroll
            for (int nt = 0; nt < 4; nt++)
#pragma unroll
                for (int e = 0; e < 4; e++) acc[mt][nt][e] = 0.0f;

#pragma unroll
        for (int s = 0; s < 3; s++) {
            const uint32_t aS = sb + (s == 2 ? xloC : xhiC);
            const uint32_t bS = sb + (s == 1 ? SM_WLO : SM_WHI);

            uint32_t a[2][4][4], b[2][2][4];
#pragma unroll
            for (int mt = 0; mt < 4; mt++) ldmx4(a[0][mt], aS + aoff[mt]);
#pragma unroll
            for (int nt2 = 0; nt2 < 2; nt2++) ldmx4(b[0][nt2], bS + boff[nt2]);

#pragma unroll
            for (int k16 = 0; k16 < 8; k16++) {
                const int pc = k16 & 1;
                const int pn = pc ^ 1;
                if (k16 < 7) {
                    const uint32_t kb = (uint32_t)((k16 + 1) * 32);
#pragma unroll
                    for (int mt = 0; mt < 4; mt++) ldmx4(a[pn][mt], aS + aoff[mt] + kb);
#pragma unroll
                    for (int nt2 = 0; nt2 < 2; nt2++) ldmx4(b[pn][nt2], bS + boff[nt2] + kb);
                }
#pragma unroll
                for (int mt = 0; mt < 4; mt++)
#pragma unroll
                    for (int nt = 0; nt < 4; nt++)
                        mma_bf16(acc[mt][nt], a[pc][mt],
                                 b[pc][nt >> 1][(nt & 1) * 2],
                                 b[pc][nt >> 1][(nt & 1) * 2 + 1]);
            }
        }

        if (more) {
#pragma unroll
            for (int k = 0; k < 16; k++) {
                const int i = tid + k * 256;
                const int row = i >> 5, c4 = i & 31;
                uint2 hi, lo;
                split4(v[k], hi, lo);
                const int off = row * PITCHB + c4 * 8;
                *reinterpret_cast<uint2*>(smem + xhiN + off) = hi;
                *reinterpret_cast<uint2*>(smem + xloN + off) = lo;
            }
        }

        const int mrow = lane >> 2;
        const int ncol = (lane & 3) * 2;
#pragma unroll
        for (int mt = 0; mt < 4; mt++) {
#pragma unroll
            for (int nt = 0; nt < 4; nt++) {
                const int col = nBase + nt * 8 + ncol;
                const float bv0 = sbias[col], bv1 = sbias[col + 1];
                const int row0 = mBase + mt * 16 + mrow;
                float* p0 = out + ((size_t)t * B_SZ + row0) * G_SZ + g0 + col;
                float* p1 = p0 + (size_t)8 * G_SZ;
                *reinterpret_cast<float2*>(p0) =
                    make_float2(acc[mt][nt][0] + bv0, acc[mt][nt][1] + bv1);
                *reinterpret_cast<float2*>(p1) =
                    make_float2(acc[mt][nt][2] + bv0, acc[mt][nt][3] + bv1);
            }
        }
        __syncthreads();
    }
}

// ---------------------------------------------------------------------------
// Recurrent scan — R1 skeleton (proven best) + three stall cuts:
//   (1) tanh via sigmoid identity (removes ~100-cyc tanhf polynomial chain)
//   (2) 4 accumulator chains in the dot (chain latency 128 -> 64 cyc)
//   (3) gate threads keep their own h in a register (one less dependent LDS)
// One CTA per batch element, 384 threads (one per gate output).
// ---------------------------------------------------------------------------
__global__ __launch_bounds__(384, 1)
void recur_kernel(const float* __restrict__ xp,
                  const float* __restrict__ W_hh,
                  const float* __restrict__ b_hh,
                  int write_y,
                  const float* __restrict__ W_out,
                  const float* __restrict__ b_out,
                  float* __restrict__ out)
{
    __shared__ __align__(16) float h_s[H_SZ];
    __shared__ float hp_s[G_SZ];
    __shared__ float xg_s[G_SZ];

    const int b = blockIdx.x;
    const int g = threadIdx.x;

    unsigned long long w[64];
    const unsigned long long* wrow =
        reinterpret_cast<const unsigned long long*>(W_hh + (size_t)g * H_SZ);
#pragma unroll
    for (int i = 0; i < 64; i++) w[i] = wrow[i];
    const float bh = b_hh[g];

    float hreg = 0.0f;                 // own h value (gate threads, g < 128)
    if (g < H_SZ) h_s[g] = 0.0f;

    const float* xptr = xp + (size_t)b * G_SZ + g;
    float xnext = __ldg(xptr);        // prefetch t=0
    __syncthreads();

    for (int t = 0; t < S_LEN; t++) {
        const float xcur = xnext;
        if (t + 1 < S_LEN)
            xnext = __ldg(xptr + (size_t)(t + 1) * B_SZ * G_SZ);  // prefetch next

        // hp[g] = h . W_hh[g] : 4 independent f32x2 chains
        unsigned long long a0 = 0ull, a1 = 0ull, a2 = 0ull, a3 = 0ull;
        const ulonglong2* hq = reinterpret_cast<const ulonglong2*>(h_s);
#pragma unroll
        for (int i = 0; i < 16; i++) {
            const ulonglong2 q0 = hq[2 * i + 0];   // broadcast LDS.128
            const ulonglong2 q1 = hq[2 * i + 1];
            a0 = fma2(q0.x, w[4 * i + 0], a0);
            a1 = fma2(q0.y, w[4 * i + 1], a1);
            a2 = fma2(q1.x, w[4 * i + 2], a2);
            a3 = fma2(q1.y, w[4 * i + 3], a3);
        }
        const unsigned long long s01 = add2(add2(a0, a1), add2(a2, a3));
        hp_s[g] = lo32(s01) + hi32(s01) + bh;
        xg_s[g] = xcur;
        __syncthreads();

        if (g < H_SZ) {
            const float pr = xg_s[g]            + hp_s[g];
            const float pz = xg_s[H_SZ + g]     + hp_s[H_SZ + g];
            const float xn = xg_s[2 * H_SZ + g];
            const float hn = hp_s[2 * H_SZ + g];
            const float r = 1.0f / (1.0f + __expf(-pr));
            const float z = 1.0f / (1.0f + __expf(-pz));
            const float ag = fmaf(r, hn, xn);
            // tanh(ag) = 2*sigmoid(2*ag) - 1  (proven at rel_err ~5e-6)
            const float sg = 1.0f / (1.0f + __expf(-2.0f * ag));
            const float n  = fmaf(2.0f, sg, -1.0f);
            const float hnew = fmaf(z, hreg - n, n);   // (1-z)*n + z*h
            hreg = hnew;
            h_s[g] = hnew;
            if (write_y)
                g_y0[((size_t)t * B_SZ + b) * H_SZ + g] = hnew;
        }
        __syncthreads();
    }

    // Fused final linear layer (layer 1 only)
    if (!write_y && g < C_SZ) {
        float acc = b_out[g];
#pragma unroll 8
        for (int j = 0; j < H_SZ; j++)
            acc = fmaf(h_s[j], W_out[g * H_SZ + j], acc);
        out[b * C_SZ + g] = acc;
    }
}

// ---------------------------------------------------------------------------
extern "C" void kernel_launch(void* const* d_in, const int* in_sizes, int n_in,
                              void* d_out, int out_size)
{
    const float* x     = (const float*)d_in[0];
    const float* W_ih0 = (const float*)d_in[1];
    const float* W_hh0 = (const float*)d_in[2];
    const float* b_ih0 = (const float*)d_in[3];
    const float* b_hh0 = (const float*)d_in[4];
    const float* W_ih1 = (const float*)d_in[5];
    const float* W_hh1 = (const float*)d_in[6];
    const float* b_ih1 = (const float*)d_in[7];
    const float* b_hh1 = (const float*)d_in[8];
    const float* W_out = (const float*)d_in[9];
    const float* b_out = (const float*)d_in[10];
    float* out = (float*)d_out;

    void* xp_ptr = nullptr;
    void* y0_ptr = nullptr;
    cudaGetSymbolAddress(&xp_ptr, g_xp);
    cudaGetSymbolAddress(&y0_ptr, g_y0);
    float* xp = (float*)xp_ptr;
    float* y0 = (float*)y0_ptr;

    cudaFuncSetAttribute(gemm_mma_kernel,
                         cudaFuncAttributeMaxDynamicSharedMemorySize, SM_TOT);

    const dim3 gemm_grid(S_LEN / TCH_T, 3);

    // Layer 0 input projection: x is [B, S, D] -> strideB = S*D, strideT = D
    gemm_mma_kernel<<<gemm_grid, 256, SM_TOT>>>(x, W_ih0, b_ih0, xp,
                                                (long)S_LEN * H_SZ, (long)H_SZ);
    // Layer 0 recurrence (writes y0)
    recur_kernel<<<B_SZ, 384>>>(xp, W_hh0, b_hh0, 1, nullptr, nullptr, nullptr);

    // Layer 1 input projection: y0 is [(t*B + b)*H] -> strideB = H, strideT = B*H
    gemm_mma_kernel<<<gemm_grid, 256, SM_TOT>>>(y0, W_ih1, b_ih1, xp,
                                                (long)H_SZ, (long)B_SZ * H_SZ);
    // Layer 1 recurrence + fused output linear
    recur_kernel<<<B_SZ, 384>>>(xp, W_hh1, b_hh1, 0, W_out, b_out, out);
}